// round 4
// baseline (speedup 1.0000x reference)
#include <cuda_runtime.h>
#include <math.h>
#include <stdint.h>

#define BATCH   2
#define SEQ     4096
#define HIDV    2048
#define DSTATE  128
#define KCONV   4
#define DIN     4096
#define HDIM    64
#define NHEAD   64
#define CHUNKL  256
#define CONVD   (DIN + 2*DSTATE)        /* 4352 */
#define PROJ    (2*(DIN+DSTATE)+NHEAD)  /* 8512 */
#define MTOK    (BATCH*SEQ)             /* 8192 */
#define TILE    32

// ---------------- scratch (no allocations allowed) ----------------
__device__ float g_zx  [(size_t)MTOK*PROJ];    // in_proj output
__device__ float g_conv[(size_t)MTOK*CONVD];   // conv+silu output
__device__ float g_dt  [MTOK*NHEAD];           // softplus(dt+bias)
__device__ float g_y   [(size_t)MTOK*DIN];     // Y then normed Y

// ---------------- shared fp32 NT GEMM core: acc = A[M,K] * B[N,K]^T ----------------
template<int BM,int BN,int TM,int TN>
__device__ __forceinline__ void gemm_nt_core(
    const float* __restrict__ A, int lda,
    const float* __restrict__ B, int ldb,
    int m0, int n0, int M, int N, int Kd,
    float (&acc)[TM][TN])
{
    __shared__ float sA[16][BM+4];
    __shared__ float sB[16][BN+4];
    const int tid = threadIdx.x;
    const int tx  = tid & 15, ty = tid >> 4;
    const int lr  = tid >> 2;            // 0..63
    const int lc  = (tid & 3) << 2;      // 0,4,8,12

#pragma unroll
    for (int i = 0; i < TM; i++)
#pragma unroll
        for (int j = 0; j < TN; j++) acc[i][j] = 0.f;

    for (int k0 = 0; k0 < Kd; k0 += 16) {
#pragma unroll
        for (int i = 0; i < BM/64; i++) {
            int r = lr + i*64;
            int gm = m0 + r;
            float4 v;
            if (gm < M) v = *reinterpret_cast<const float4*>(A + (size_t)gm*lda + k0 + lc);
            else        v = make_float4(0.f,0.f,0.f,0.f);
            sA[lc+0][r]=v.x; sA[lc+1][r]=v.y; sA[lc+2][r]=v.z; sA[lc+3][r]=v.w;
        }
#pragma unroll
        for (int i = 0; i < BN/64; i++) {
            int r = lr + i*64;
            int gn = n0 + r;
            float4 v;
            if (gn < N) v = *reinterpret_cast<const float4*>(B + (size_t)gn*ldb + k0 + lc);
            else        v = make_float4(0.f,0.f,0.f,0.f);
            sB[lc+0][r]=v.x; sB[lc+1][r]=v.y; sB[lc+2][r]=v.z; sB[lc+3][r]=v.w;
        }
        __syncthreads();
#pragma unroll
        for (int kk = 0; kk < 16; kk++) {
            float av[TM], bv[TN];
#pragma unroll
            for (int i = 0; i < TM; i += 4) {
                float4 t = *reinterpret_cast<const float4*>(&sA[kk][ty*TM+i]);
                av[i]=t.x; av[i+1]=t.y; av[i+2]=t.z; av[i+3]=t.w;
            }
#pragma unroll
            for (int j = 0; j < TN; j += 4) {
                float4 t = *reinterpret_cast<const float4*>(&sB[kk][tx*TN+j]);
                bv[j]=t.x; bv[j+1]=t.y; bv[j+2]=t.z; bv[j+3]=t.w;
            }
#pragma unroll
            for (int i = 0; i < TM; i++)
#pragma unroll
                for (int j = 0; j < TN; j++)
                    acc[i][j] = fmaf(av[i], bv[j], acc[i][j]);
        }
        __syncthreads();
    }
}

// ---------------- big GEMMs ----------------
__global__ void __launch_bounds__(256) gemm_plain(
    const float* A, int lda, const float* B, int ldb,
    float* C, int ldc, int M, int N, int Kd)
{
    const float* Ap = A ? A : g_y;
    float*       Cp = C ? C : g_zx;
    int m0 = blockIdx.y * 128, n0 = blockIdx.x * 128;
    float acc[8][8];
    gemm_nt_core<128,128,8,8>(Ap, lda, B, ldb, m0, n0, M, N, Kd, acc);
    int tx = threadIdx.x & 15, ty = threadIdx.x >> 4;
#pragma unroll
    for (int i = 0; i < 8; i++) {
        int m = m0 + ty*8 + i;
        if (m >= M) continue;
#pragma unroll
        for (int j = 0; j < 8; j++) {
            int n = n0 + tx*8 + j;
            if (n < N) Cp[(size_t)m*ldc + n] = acc[i][j];
        }
    }
}

// ---------------- causal conv1d (K=4) + bias + silu ----------------
__global__ void conv_kernel(const float* __restrict__ w, const float* __restrict__ bias)
{
    int m  = blockIdx.x;
    int ch = blockIdx.y*256 + threadIdx.x;          // < 4352
    int t  = m & (SEQ-1);
    float acc = bias[ch];
#pragma unroll
    for (int i = 0; i < KCONV; i++) {
        int tt = t - (KCONV-1) + i;
        if (tt >= 0)
            acc += g_zx[(size_t)(m - (KCONV-1) + i)*PROJ + DIN + ch] * w[ch*KCONV + i];
    }
    acc = acc / (1.f + expf(-acc));                 // silu
    g_conv[(size_t)m*CONVD + ch] = acc;
}

// ---------------- dt = softplus(dt_raw + dt_bias) ----------------
__global__ void dt_kernel(const float* __restrict__ dtb)
{
    int id = blockIdx.x*256 + threadIdx.x;          // m*64+h
    int m = id >> 6, h = id & 63;
    float v = g_zx[(size_t)m*PROJ + DIN + CONVD + h] + dtb[h];
    g_dt[id] = (v > 20.f) ? v : log1pf(expf(v));
}

// ---------------- SSD as the exact sequential recurrence ----------------
// One block per (h, b). 512 threads: p = tid>>3 (0..63), q = tid&7 (0..7).
// Thread owns H[p][j*16 + q*2 + {0,1}] for j = 0..7  (16 floats).
//   H <- exp(A*dt_l) * H + dt_l * x[l,p] (x) B[l,:]
//   y[l,p] = C[l,:] . H[p,:] + D_h * x[l,p]
// This equals Yd + Yo + x*D of the reference (chunked form is an algebraic
// refactoring of this recurrence).
__global__ void __launch_bounds__(512) ssd_kernel(const float* __restrict__ A_log,
                                                  const float* __restrict__ Dv)
{
    const int h = blockIdx.x;
    const int b = blockIdx.y;
    const int tid = threadIdx.x;
    const int p = tid >> 3, q = tid & 7;

    __shared__ float sB[TILE][DSTATE];   // 16KB
    __shared__ float sC[TILE][DSTATE];   // 16KB
    __shared__ float sX[TILE][HDIM];     // 8KB
    __shared__ float s_dt[TILE], s_eadt[TILE];

    const float A  = -expf(A_log[h]);
    const float Dh = Dv[h];

    float H[16];
#pragma unroll
    for (int j = 0; j < 16; j++) H[j] = 0.f;

    for (int t0 = 0; t0 < SEQ; t0 += TILE) {
        const size_t mbase = (size_t)b*SEQ + t0;

        // stage B and C tiles (2048 float4 total)
#pragma unroll
        for (int it = 0; it < 4; it++) {
            int idx = it*512 + tid;
            int r = idx >> 6, c = idx & 63;
            const float* rowp = g_conv + (mbase + r)*CONVD + DIN;
            if (c < 32) *(float4*)&sB[r][c*4]      = *(const float4*)(rowp + c*4);
            else        *(float4*)&sC[r][(c-32)*4] = *(const float4*)(rowp + DSTATE + (c-32)*4);
        }
        // stage x tile (512 float4)
        {
            int r = tid >> 4, c = tid & 15;
            *(float4*)&sX[r][c*4] =
                *(const float4*)(g_conv + (mbase + r)*CONVD + h*HDIM + c*4);
        }
        // stage dt + decay
        if (tid < TILE) {
            float dtv = g_dt[(mbase + tid)*NHEAD + h];
            s_dt[tid]   = dtv;
            s_eadt[tid] = expf(A * dtv);
        }
        __syncthreads();

        for (int ll = 0; ll < TILE; ll++) {
            float e = s_eadt[ll];
            float f = s_dt[ll] * sX[ll][p];
            float part = 0.f;
#pragma unroll
            for (int j = 0; j < 8; j++) {
                int col = j*16 + q*2;
                float2 bb = *(const float2*)&sB[ll][col];
                float2 cc = *(const float2*)&sC[ll][col];
                H[2*j]   = e*H[2*j]   + f*bb.x;
                H[2*j+1] = e*H[2*j+1] + f*bb.y;
                part += cc.x*H[2*j] + cc.y*H[2*j+1];
            }
            part += __shfl_down_sync(0xffffffffu, part, 4, 8);
            part += __shfl_down_sync(0xffffffffu, part, 2, 8);
            part += __shfl_down_sync(0xffffffffu, part, 1, 8);
            if (q == 0)
                g_y[(mbase + ll)*DIN + h*HDIM + p] = part + Dh * sX[ll][p];
        }
        __syncthreads();
    }
}

// ---------------- gated RMSNorm (in-place on g_y) ----------------
__global__ void __launch_bounds__(256) rmsnorm_kernel(const float* __restrict__ w)
{
    int m = blockIdx.x;
    int tid = threadIdx.x;
    float prod[16];
    float ss = 0.f;
#pragma unroll
    for (int i = 0; i < 16; i++) {
        int col = i*256 + tid;
        float y = g_y[(size_t)m*DIN + col];
        float z = g_zx[(size_t)m*PROJ + col];
        float p = y * (z / (1.f + expf(-z)));
        prod[i] = p;
        ss += p*p;
    }
    __shared__ float red[256];
    red[tid] = ss;
    __syncthreads();
    for (int off = 128; off; off >>= 1) {
        if (tid < off) red[tid] += red[tid + off];
        __syncthreads();
    }
    float scale = rsqrtf(red[0] / (float)DIN + 1e-5f);
#pragma unroll
    for (int i = 0; i < 16; i++) {
        int col = i*256 + tid;
        g_y[(size_t)m*DIN + col] = prod[i] * scale * w[col];
    }
}

// ---------------- launch ----------------
extern "C" void kernel_launch(void* const* d_in, const int* in_sizes, int n_in,
                              void* d_out, int out_size)
{
    const float* hs   = (const float*)d_in[0];
    const float* w1   = (const float*)d_in[1];
    const float* cw   = (const float*)d_in[2];
    const float* cb   = (const float*)d_in[3];
    const float* dtb  = (const float*)d_in[4];
    const float* alog = (const float*)d_in[5];
    const float* Dv   = (const float*)d_in[6];
    const float* nw   = (const float*)d_in[7];
    const float* w2   = (const float*)d_in[8];
    float* out = (float*)d_out;

    // 1. in_proj GEMM: g_zx[8192,8512] = hs @ w1^T
    gemm_plain<<<dim3((PROJ+127)/128, MTOK/128), 256>>>(hs, HIDV, w1, HIDV,
                                                        nullptr, PROJ, MTOK, PROJ, HIDV);
    // 2. conv + silu
    conv_kernel<<<dim3(MTOK, CONVD/256), 256>>>(cw, cb);
    // 3. dt softplus
    dt_kernel<<<(MTOK*NHEAD)/256, 256>>>(dtb);
    // 4. SSD recurrence
    ssd_kernel<<<dim3(NHEAD, BATCH), 512>>>(alog, Dv);
    // 5. gated rmsnorm
    rmsnorm_kernel<<<MTOK, 256>>>(nw);
    // 6. out_proj GEMM: out[8192,2048] = g_y @ w2^T
    gemm_plain<<<dim3(HIDV/128, MTOK/128), 256>>>(nullptr, DIN, w2, DIN,
                                                  out, HIDV, MTOK, HIDV, DIN);
}

// round 6
// speedup vs baseline: 1.8463x; 1.8463x over previous
#include <cuda_runtime.h>
#include <cuda_bf16.h>
#include <math.h>
#include <stdint.h>

#define BATCH   2
#define SEQ     4096
#define HIDV    2048
#define DSTATE  128
#define KCONV   4
#define DIN     4096
#define HDIM    64
#define NHEAD   64
#define CONVD   (DIN + 2*DSTATE)        /* 4352 */
#define PROJ    (2*(DIN+DSTATE)+NHEAD)  /* 8512 */
#define MTOK    (BATCH*SEQ)             /* 8192 */
#define TILE    32

// ---------------- scratch (no allocations allowed) ----------------
__device__ float g_zx  [(size_t)MTOK*PROJ];    // in_proj output
__device__ float g_conv[(size_t)MTOK*CONVD];   // conv+silu output
__device__ float g_dt  [MTOK*NHEAD];           // softplus(dt+bias)
__device__ float g_y   [(size_t)MTOK*DIN];     // Y then normed Y

// ---------------- mma.sync m16n8k16 bf16 (baseline PTX, assembles on sm_103) ----------------
__device__ __forceinline__ void mma16816(float* d, const uint32_t* a, const uint32_t* b) {
    asm volatile(
        "mma.sync.aligned.m16n8k16.row.col.f32.bf16.bf16.f32 "
        "{%0,%1,%2,%3}, {%4,%5,%6,%7}, {%8,%9}, {%0,%1,%2,%3};"
        : "+f"(d[0]), "+f"(d[1]), "+f"(d[2]), "+f"(d[3])
        : "r"(a[0]), "r"(a[1]), "r"(a[2]), "r"(a[3]), "r"(b[0]), "r"(b[1]));
}

// ============ tensor-core GEMM: C[M,N] = A[M,K] * B[N,K]^T (fp32 in/out) ============
// bf16 hi/lo split: C ~= Ahi*Bhi + Ahi*Blo + Alo*Bhi
// CTA tile 128x128, BK=32, 8 warps in 2(m) x 4(n), warp tile 64x32.
#define BK   32
#define SAK  40     /* padded k-stride in bf16 elems (80B rows; frag loads conflict-free) */

__global__ void __launch_bounds__(256) gemm_mma(
    const float* A, int lda, const float* B, int ldb,
    float* C, int ldc, int M, int N, int Kd)
{
    const float* Ap = A ? A : g_y;
    float*       Cp = C ? C : g_zx;

    __shared__ __nv_bfloat16 sA[2][128][SAK];   // [hi/lo][m][k]  20KB
    __shared__ __nv_bfloat16 sB[2][128][SAK];   // [hi/lo][n][k]  20KB

    const int tid  = threadIdx.x;
    const int lane = tid & 31, wid = tid >> 5;
    const int wm = wid & 1, wn = wid >> 1;      // warp grid 2 x 4
    const int lr = lane >> 2, lc = lane & 3;
    const int m0 = blockIdx.y * 128, n0 = blockIdx.x * 128;

    float d[4][4][4];                            // [mi][ni][reg]
#pragma unroll
    for (int mi = 0; mi < 4; mi++)
#pragma unroll
        for (int ni = 0; ni < 4; ni++)
#pragma unroll
            for (int r = 0; r < 4; r++) d[mi][ni][r] = 0.f;

    for (int k0 = 0; k0 < Kd; k0 += BK) {
        // ---- stage A,B chunks: fp32 -> bf16 hi/lo into smem ----
#pragma unroll
        for (int it = 0; it < 4; it++) {
            int idx = it*256 + tid;              // 0..1023
            int r = idx >> 3, c = (idx & 7) * 4; // row, col(floats)
            float4 v = *reinterpret_cast<const float4*>(Ap + (size_t)(m0 + r)*lda + k0 + c);
            __nv_bfloat16 h0=__float2bfloat16_rn(v.x), h1=__float2bfloat16_rn(v.y),
                          h2=__float2bfloat16_rn(v.z), h3=__float2bfloat16_rn(v.w);
            *reinterpret_cast<__nv_bfloat162*>(&sA[0][r][c])   = __nv_bfloat162(h0, h1);
            *reinterpret_cast<__nv_bfloat162*>(&sA[0][r][c+2]) = __nv_bfloat162(h2, h3);
            *reinterpret_cast<__nv_bfloat162*>(&sA[1][r][c])   = __nv_bfloat162(
                __float2bfloat16_rn(v.x-__bfloat162float(h0)),
                __float2bfloat16_rn(v.y-__bfloat162float(h1)));
            *reinterpret_cast<__nv_bfloat162*>(&sA[1][r][c+2]) = __nv_bfloat162(
                __float2bfloat16_rn(v.z-__bfloat162float(h2)),
                __float2bfloat16_rn(v.w-__bfloat162float(h3)));
        }
#pragma unroll
        for (int it = 0; it < 4; it++) {
            int idx = it*256 + tid;
            int r = idx >> 3, c = (idx & 7) * 4;
            int gn = n0 + r;
            float4 v = make_float4(0.f, 0.f, 0.f, 0.f);
            if (gn < N) v = *reinterpret_cast<const float4*>(B + (size_t)gn*ldb + k0 + c);
            __nv_bfloat16 h0=__float2bfloat16_rn(v.x), h1=__float2bfloat16_rn(v.y),
                          h2=__float2bfloat16_rn(v.z), h3=__float2bfloat16_rn(v.w);
            *reinterpret_cast<__nv_bfloat162*>(&sB[0][r][c])   = __nv_bfloat162(h0, h1);
            *reinterpret_cast<__nv_bfloat162*>(&sB[0][r][c+2]) = __nv_bfloat162(h2, h3);
            *reinterpret_cast<__nv_bfloat162*>(&sB[1][r][c])   = __nv_bfloat162(
                __float2bfloat16_rn(v.x-__bfloat162float(h0)),
                __float2bfloat16_rn(v.y-__bfloat162float(h1)));
            *reinterpret_cast<__nv_bfloat162*>(&sB[1][r][c+2]) = __nv_bfloat162(
                __float2bfloat16_rn(v.z-__bfloat162float(h2)),
                __float2bfloat16_rn(v.w-__bfloat162float(h3)));
        }
        __syncthreads();

        // ---- compute: 2 k-steps of 16 ----
#pragma unroll
        for (int ks = 0; ks < BK; ks += 16) {
            uint32_t ah[4][4], al[4][4], bh[4][2], bl[4][2];
#pragma unroll
            for (int mi = 0; mi < 4; mi++) {
                int row = wm*64 + mi*16 + lr;
                int kk  = ks + lc*2;
                ah[mi][0] = *reinterpret_cast<const uint32_t*>(&sA[0][row  ][kk  ]);
                ah[mi][1] = *reinterpret_cast<const uint32_t*>(&sA[0][row+8][kk  ]);
                ah[mi][2] = *reinterpret_cast<const uint32_t*>(&sA[0][row  ][kk+8]);
                ah[mi][3] = *reinterpret_cast<const uint32_t*>(&sA[0][row+8][kk+8]);
                al[mi][0] = *reinterpret_cast<const uint32_t*>(&sA[1][row  ][kk  ]);
                al[mi][1] = *reinterpret_cast<const uint32_t*>(&sA[1][row+8][kk  ]);
                al[mi][2] = *reinterpret_cast<const uint32_t*>(&sA[1][row  ][kk+8]);
                al[mi][3] = *reinterpret_cast<const uint32_t*>(&sA[1][row+8][kk+8]);
            }
#pragma unroll
            for (int ni = 0; ni < 4; ni++) {
                int row = wn*32 + ni*8 + lr;
                int kk  = ks + lc*2;
                bh[ni][0] = *reinterpret_cast<const uint32_t*>(&sB[0][row][kk  ]);
                bh[ni][1] = *reinterpret_cast<const uint32_t*>(&sB[0][row][kk+8]);
                bl[ni][0] = *reinterpret_cast<const uint32_t*>(&sB[1][row][kk  ]);
                bl[ni][1] = *reinterpret_cast<const uint32_t*>(&sB[1][row][kk+8]);
            }
#pragma unroll
            for (int mi = 0; mi < 4; mi++)
#pragma unroll
                for (int ni = 0; ni < 4; ni++) {
                    mma16816(d[mi][ni], ah[mi], bh[ni]);
                    mma16816(d[mi][ni], ah[mi], bl[ni]);
                    mma16816(d[mi][ni], al[mi], bh[ni]);
                }
        }
        __syncthreads();
    }

    // ---- epilogue ----
#pragma unroll
    for (int mi = 0; mi < 4; mi++) {
        int m = m0 + wm*64 + mi*16 + lr;
#pragma unroll
        for (int ni = 0; ni < 4; ni++) {
            int n = n0 + wn*32 + ni*8 + lc*2;
            if (n < N) {
                *reinterpret_cast<float2*>(Cp + (size_t)m*ldc + n) =
                    make_float2(d[mi][ni][0], d[mi][ni][1]);
                *reinterpret_cast<float2*>(Cp + (size_t)(m+8)*ldc + n) =
                    make_float2(d[mi][ni][2], d[mi][ni][3]);
            }
        }
    }
}

// ---------------- causal conv1d (K=4) + bias + silu ----------------
__global__ void conv_kernel(const float* __restrict__ w, const float* __restrict__ bias)
{
    int m  = blockIdx.x;
    int ch = blockIdx.y*256 + threadIdx.x;          // < 4352
    int t  = m & (SEQ-1);
    float acc = bias[ch];
#pragma unroll
    for (int i = 0; i < KCONV; i++) {
        int tt = t - (KCONV-1) + i;
        if (tt >= 0)
            acc += g_zx[(size_t)(m - (KCONV-1) + i)*PROJ + DIN + ch] * w[ch*KCONV + i];
    }
    acc = acc / (1.f + expf(-acc));                 // silu
    g_conv[(size_t)m*CONVD + ch] = acc;
}

// ---------------- dt = softplus(dt_raw + dt_bias) ----------------
__global__ void dt_kernel(const float* __restrict__ dtb)
{
    int id = blockIdx.x*256 + threadIdx.x;          // m*64+h
    int m = id >> 6, h = id & 63;
    float v = g_zx[(size_t)m*PROJ + DIN + CONVD + h] + dtb[h];
    g_dt[id] = (v > 20.f) ? v : log1pf(expf(v));
}

// ---------------- SSD as the exact sequential recurrence ----------------
__global__ void __launch_bounds__(512) ssd_kernel(const float* __restrict__ A_log,
                                                  const float* __restrict__ Dv)
{
    const int h = blockIdx.x;
    const int b = blockIdx.y;
    const int tid = threadIdx.x;
    const int p = tid >> 3, q = tid & 7;

    __shared__ float sB[TILE][DSTATE];
    __shared__ float sC[TILE][DSTATE];
    __shared__ float sX[TILE][HDIM];
    __shared__ float s_dt[TILE], s_eadt[TILE];

    const float A  = -expf(A_log[h]);
    const float Dh = Dv[h];

    float H[16];
#pragma unroll
    for (int j = 0; j < 16; j++) H[j] = 0.f;

    for (int t0 = 0; t0 < SEQ; t0 += TILE) {
        const size_t mbase = (size_t)b*SEQ + t0;
#pragma unroll
        for (int it = 0; it < 4; it++) {
            int idx = it*512 + tid;
            int r = idx >> 6, c = idx & 63;
            const float* rowp = g_conv + (mbase + r)*CONVD + DIN;
            if (c < 32) *(float4*)&sB[r][c*4]      = *(const float4*)(rowp + c*4);
            else        *(float4*)&sC[r][(c-32)*4] = *(const float4*)(rowp + DSTATE + (c-32)*4);
        }
        {
            int r = tid >> 4, c = tid & 15;
            *(float4*)&sX[r][c*4] =
                *(const float4*)(g_conv + (mbase + r)*CONVD + h*HDIM + c*4);
        }
        if (tid < TILE) {
            float dtv = g_dt[(mbase + tid)*NHEAD + h];
            s_dt[tid]   = dtv;
            s_eadt[tid] = expf(A * dtv);
        }
        __syncthreads();

        for (int ll = 0; ll < TILE; ll++) {
            float e = s_eadt[ll];
            float f = s_dt[ll] * sX[ll][p];
            float part = 0.f;
#pragma unroll
            for (int j = 0; j < 8; j++) {
                int col = j*16 + q*2;
                float2 bb = *(const float2*)&sB[ll][col];
                float2 cc = *(const float2*)&sC[ll][col];
                H[2*j]   = e*H[2*j]   + f*bb.x;
                H[2*j+1] = e*H[2*j+1] + f*bb.y;
                part += cc.x*H[2*j] + cc.y*H[2*j+1];
            }
            part += __shfl_down_sync(0xffffffffu, part, 4, 8);
            part += __shfl_down_sync(0xffffffffu, part, 2, 8);
            part += __shfl_down_sync(0xffffffffu, part, 1, 8);
            if (q == 0)
                g_y[(mbase + ll)*DIN + h*HDIM + p] = part + Dh * sX[ll][p];
        }
        __syncthreads();
    }
}

// ---------------- gated RMSNorm (in-place on g_y) ----------------
__global__ void __launch_bounds__(256) rmsnorm_kernel(const float* __restrict__ w)
{
    int m = blockIdx.x;
    int tid = threadIdx.x;
    float prod[16];
    float ss = 0.f;
#pragma unroll
    for (int i = 0; i < 16; i++) {
        int col = i*256 + tid;
        float y = g_y[(size_t)m*DIN + col];
        float z = g_zx[(size_t)m*PROJ + col];
        float p = y * (z / (1.f + expf(-z)));
        prod[i] = p;
        ss += p*p;
    }
    __shared__ float red[256];
    red[tid] = ss;
    __syncthreads();
    for (int off = 128; off; off >>= 1) {
        if (tid < off) red[tid] += red[tid + off];
        __syncthreads();
    }
    float scale = rsqrtf(red[0] / (float)DIN + 1e-5f);
#pragma unroll
    for (int i = 0; i < 16; i++) {
        int col = i*256 + tid;
        g_y[(size_t)m*DIN + col] = prod[i] * scale * w[col];
    }
}

// ---------------- launch ----------------
extern "C" void kernel_launch(void* const* d_in, const int* in_sizes, int n_in,
                              void* d_out, int out_size)
{
    const float* hs   = (const float*)d_in[0];
    const float* w1   = (const float*)d_in[1];
    const float* cw   = (const float*)d_in[2];
    const float* cb   = (const float*)d_in[3];
    const float* dtb  = (const float*)d_in[4];
    const float* alog = (const float*)d_in[5];
    const float* Dv   = (const float*)d_in[6];
    const float* nw   = (const float*)d_in[7];
    const float* w2   = (const float*)d_in[8];
    float* out = (float*)d_out;

    // 1. in_proj GEMM: g_zx[8192,8512] = hs @ w1^T
    gemm_mma<<<dim3((PROJ+127)/128, MTOK/128), 256>>>(
        hs, HIDV, w1, HIDV, nullptr, PROJ, MTOK, PROJ, HIDV);
    // 2. conv + silu
    conv_kernel<<<dim3(MTOK, CONVD/256), 256>>>(cw, cb);
    // 3. dt softplus
    dt_kernel<<<(MTOK*NHEAD)/256, 256>>>(dtb);
    // 4. SSD recurrence
    ssd_kernel<<<dim3(NHEAD, BATCH), 512>>>(alog, Dv);
    // 5. gated rmsnorm
    rmsnorm_kernel<<<MTOK, 256>>>(nw);
    // 6. out_proj GEMM: out[8192,2048] = g_y @ w2^T
    gemm_mma<<<dim3(HIDV/128, MTOK/128), 256>>>(
        nullptr, DIN, w2, DIN, out, HIDV, MTOK, HIDV, DIN);
}

// round 7
// speedup vs baseline: 2.2953x; 1.2432x over previous
#include <cuda_runtime.h>
#include <cuda_bf16.h>
#include <math.h>
#include <stdint.h>

#define BATCH   2
#define SEQ     4096
#define HIDV    2048
#define DSTATE  128
#define KCONV   4
#define DIN     4096
#define HDIM    64
#define NHEAD   64
#define CONVD   (DIN + 2*DSTATE)        /* 4352 */
#define PROJ    (2*(DIN+DSTATE)+NHEAD)  /* 8512 */
#define MTOK    (BATCH*SEQ)             /* 8192 */
#define TILE    32

// ---------------- scratch (no allocations allowed) ----------------
__device__ float g_zx  [(size_t)MTOK*PROJ];    // in_proj output (fp32)
__device__ float g_conv[(size_t)MTOK*CONVD];   // conv+silu output
__device__ float g_dt  [MTOK*NHEAD];           // softplus(dt+bias)
__device__ float g_y   [(size_t)MTOK*DIN];     // SSD output (pre-norm)

// bf16 hi/lo planes for tensor-core GEMMs
__device__ __nv_bfloat16 g_hs_hi[(size_t)MTOK*HIDV], g_hs_lo[(size_t)MTOK*HIDV];
__device__ __nv_bfloat16 g_w1_hi[(size_t)PROJ*HIDV], g_w1_lo[(size_t)PROJ*HIDV];
__device__ __nv_bfloat16 g_w2_hi[(size_t)HIDV*DIN],  g_w2_lo[(size_t)HIDV*DIN];
__device__ __nv_bfloat16 g_yn_hi[(size_t)MTOK*DIN],  g_yn_lo[(size_t)MTOK*DIN];

// ---------------- helpers ----------------
__device__ __forceinline__ uint32_t smem_u32(const void* p) {
    uint32_t a;
    asm("{ .reg .u64 t; cvta.to.shared.u64 t, %1; cvt.u32.u64 %0, t; }" : "=r"(a) : "l"(p));
    return a;
}
__device__ __forceinline__ void cp_async16(uint32_t dst, const void* src, int srcsize) {
    asm volatile("cp.async.ca.shared.global [%0], [%1], 16, %2;"
                 :: "r"(dst), "l"(src), "r"(srcsize) : "memory");
}
#define CP_COMMIT() asm volatile("cp.async.commit_group;" ::: "memory")
#define CP_WAIT0()  asm volatile("cp.async.wait_group 0;" ::: "memory")
#define CP_WAIT1()  asm volatile("cp.async.wait_group 1;" ::: "memory")

__device__ __forceinline__ void ldmx4(uint32_t* r, uint32_t addr) {
    asm volatile("ldmatrix.sync.aligned.m8n8.x4.shared.b16 {%0,%1,%2,%3}, [%4];"
                 : "=r"(r[0]), "=r"(r[1]), "=r"(r[2]), "=r"(r[3]) : "r"(addr));
}
__device__ __forceinline__ void mma16816(float* d, const uint32_t* a, const uint32_t* b) {
    asm volatile(
        "mma.sync.aligned.m16n8k16.row.col.f32.bf16.bf16.f32 "
        "{%0,%1,%2,%3}, {%4,%5,%6,%7}, {%8,%9}, {%0,%1,%2,%3};"
        : "+f"(d[0]), "+f"(d[1]), "+f"(d[2]), "+f"(d[3])
        : "r"(a[0]), "r"(a[1]), "r"(a[2]), "r"(a[3]), "r"(b[0]), "r"(b[1]));
}

// ---------------- fp32 -> bf16 hi/lo split (pre-convert) ----------------
__global__ void convert_kernel(const float* __restrict__ src, int dst_sel, size_t n4)
{
    size_t i = (size_t)blockIdx.x*256 + threadIdx.x;
    if (i >= n4) return;
    __nv_bfloat16 *hi, *lo;
    if (dst_sel == 0)      { hi = g_hs_hi; lo = g_hs_lo; }
    else if (dst_sel == 1) { hi = g_w1_hi; lo = g_w1_lo; }
    else                   { hi = g_w2_hi; lo = g_w2_lo; }
    float4 v = reinterpret_cast<const float4*>(src)[i];
    __nv_bfloat16 h0=__float2bfloat16_rn(v.x), h1=__float2bfloat16_rn(v.y),
                  h2=__float2bfloat16_rn(v.z), h3=__float2bfloat16_rn(v.w);
    reinterpret_cast<__nv_bfloat162*>(hi)[i*2]   = __nv_bfloat162(h0, h1);
    reinterpret_cast<__nv_bfloat162*>(hi)[i*2+1] = __nv_bfloat162(h2, h3);
    reinterpret_cast<__nv_bfloat162*>(lo)[i*2]   = __nv_bfloat162(
        __float2bfloat16_rn(v.x-__bfloat162float(h0)),
        __float2bfloat16_rn(v.y-__bfloat162float(h1)));
    reinterpret_cast<__nv_bfloat162*>(lo)[i*2+1] = __nv_bfloat162(
        __float2bfloat16_rn(v.z-__bfloat162float(h2)),
        __float2bfloat16_rn(v.w-__bfloat162float(h3)));
}

// ============ tensor-core GEMM: C[M,N] = A[M,K]*B[N,K]^T, bf16 3-pass split ============
// CTA 128x128, BK=32, double-buffered cp.async, ldmatrix fragments.
#define BK      32
#define SAK_B   80                      /* padded row stride in bytes (40 bf16) */
#define PLANE_B (128*SAK_B)             /* 10240 B per plane              */
#define BUF_B   (4*PLANE_B)             /* Ahi Alo Bhi Blo = 40960 B      */
#define SMT     (2*BUF_B)               /* 81920 B total                  */

__global__ void __launch_bounds__(256) gemm_mma(int which, float* Cout, int M, int N, int Kd)
{
    extern __shared__ char sm[];
    const __nv_bfloat16 *Ah, *Al, *Bh, *Bl;
    float* Cp;
    if (which == 0) { Ah=g_hs_hi; Al=g_hs_lo; Bh=g_w1_hi; Bl=g_w1_lo; Cp=g_zx; }
    else            { Ah=g_yn_hi; Al=g_yn_lo; Bh=g_w2_hi; Bl=g_w2_lo; Cp=Cout; }

    const uint32_t sb = smem_u32(sm);
    const int tid  = threadIdx.x;
    const int lane = tid & 31, wid = tid >> 5;
    const int wm = wid & 1, wn = wid >> 1;          // 2 x 4 warp grid
    const int lr = lane >> 2, lc = lane & 3;
    const int m0 = blockIdx.y * 128, n0 = blockIdx.x * 128;
    const int nk = Kd / BK;

    // staging: 8 cp.async per thread (A: 4 iters, B: 4 iters)
    auto stage = [&](int kc, int buf) {
        const int k0 = kc * BK;
        const uint32_t base = sb + buf * BUF_B;
#pragma unroll
        for (int it = 0; it < 4; it++) {
            int idx = it*256 + tid;                  // 0..1023
            int pl  = idx >> 9;                      // 0=hi 1=lo
            int row = (idx >> 2) & 127, ch = idx & 3;
            const __nv_bfloat16* s = (pl ? Al : Ah) + (size_t)(m0 + row)*Kd + k0 + ch*8;
            cp_async16(base + pl*PLANE_B + row*SAK_B + ch*16, s, 16);
        }
#pragma unroll
        for (int it = 0; it < 4; it++) {
            int idx = it*256 + tid;
            int pl  = idx >> 9;
            int row = (idx >> 2) & 127, ch = idx & 3;
            int gn = n0 + row;
            const __nv_bfloat16* s = (pl ? Bl : Bh) + (size_t)gn*Kd + k0 + ch*8;
            cp_async16(base + (2+pl)*PLANE_B + row*SAK_B + ch*16, s, gn < N ? 16 : 0);
        }
    };

    float d[4][4][4];
#pragma unroll
    for (int mi = 0; mi < 4; mi++)
#pragma unroll
        for (int ni = 0; ni < 4; ni++)
#pragma unroll
            for (int r = 0; r < 4; r++) d[mi][ni][r] = 0.f;

    stage(0, 0); CP_COMMIT();

    for (int k = 0; k < nk; k++) {
        const int buf = k & 1;
        if (k + 1 < nk) { stage(k + 1, buf ^ 1); CP_COMMIT(); CP_WAIT1(); }
        else            { CP_WAIT0(); }
        __syncthreads();

        const uint32_t base = sb + buf * BUF_B;
        // lane address components (shared by both k-steps, add ks*2 bytes offset)
        const int arow = wm*64 + (lane & 15);
        const int akof = (lane & 16) ? 16 : 0;       // bytes (8 bf16)
        const int bkof = (lane & 8)  ? 16 : 0;
#pragma unroll
        for (int ks = 0; ks < BK; ks += 16) {
            uint32_t ah[4][4], al[4][4], bh[2][4], bl[2][4];
#pragma unroll
            for (int mi = 0; mi < 4; mi++) {
                uint32_t ao = (uint32_t)((arow + mi*16)*SAK_B + ks*2 + akof);
                ldmx4(ah[mi], base + ao);
                ldmx4(al[mi], base + PLANE_B + ao);
            }
#pragma unroll
            for (int pr = 0; pr < 2; pr++) {
                int brow = wn*32 + pr*16 + (lane & 7) + ((lane & 16) ? 8 : 0);
                uint32_t bo = (uint32_t)(brow*SAK_B + ks*2 + bkof);
                ldmx4(bh[pr], base + 2*PLANE_B + bo);
                ldmx4(bl[pr], base + 3*PLANE_B + bo);
            }
#pragma unroll
            for (int mi = 0; mi < 4; mi++)
#pragma unroll
                for (int ni = 0; ni < 4; ni++) {
                    const uint32_t* bhp = &bh[ni>>1][(ni&1)*2];
                    const uint32_t* blp = &bl[ni>>1][(ni&1)*2];
                    mma16816(d[mi][ni], ah[mi], bhp);
                    mma16816(d[mi][ni], ah[mi], blp);
                    mma16816(d[mi][ni], al[mi], bhp);
                }
        }
        __syncthreads();
    }

    // epilogue
#pragma unroll
    for (int mi = 0; mi < 4; mi++) {
        int m = m0 + wm*64 + mi*16 + lr;
#pragma unroll
        for (int ni = 0; ni < 4; ni++) {
            int n = n0 + wn*32 + ni*8 + lc*2;
            if (n < N) {
                *reinterpret_cast<float2*>(Cp + (size_t)m*N + n) =
                    make_float2(d[mi][ni][0], d[mi][ni][1]);
                *reinterpret_cast<float2*>(Cp + (size_t)(m+8)*N + n) =
                    make_float2(d[mi][ni][2], d[mi][ni][3]);
            }
        }
    }
}

// ---------------- causal conv1d (K=4) + bias + silu ----------------
__global__ void conv_kernel(const float* __restrict__ w, const float* __restrict__ bias)
{
    int m  = blockIdx.x;
    int ch = blockIdx.y*256 + threadIdx.x;          // < 4352
    int t  = m & (SEQ-1);
    float acc = bias[ch];
#pragma unroll
    for (int i = 0; i < KCONV; i++) {
        int tt = t - (KCONV-1) + i;
        if (tt >= 0)
            acc += g_zx[(size_t)(m - (KCONV-1) + i)*PROJ + DIN + ch] * w[ch*KCONV + i];
    }
    acc = acc / (1.f + expf(-acc));                 // silu
    g_conv[(size_t)m*CONVD + ch] = acc;
}

// ---------------- dt = softplus(dt_raw + dt_bias) ----------------
__global__ void dt_kernel(const float* __restrict__ dtb)
{
    int id = blockIdx.x*256 + threadIdx.x;          // m*64+h
    int m = id >> 6, h = id & 63;
    float v = g_zx[(size_t)m*PROJ + DIN + CONVD + h] + dtb[h];
    g_dt[id] = (v > 20.f) ? v : log1pf(expf(v));
}

// ---------------- SSD as the exact sequential recurrence ----------------
__global__ void __launch_bounds__(512) ssd_kernel(const float* __restrict__ A_log,
                                                  const float* __restrict__ Dv)
{
    const int h = blockIdx.x;
    const int b = blockIdx.y;
    const int tid = threadIdx.x;
    const int p = tid >> 3, q = tid & 7;

    __shared__ float sB[TILE][DSTATE];
    __shared__ float sC[TILE][DSTATE];
    __shared__ float sX[TILE][HDIM];
    __shared__ float s_dt[TILE], s_eadt[TILE];

    const float A  = -expf(A_log[h]);
    const float Dh = Dv[h];

    float H[16];
#pragma unroll
    for (int j = 0; j < 16; j++) H[j] = 0.f;

    for (int t0 = 0; t0 < SEQ; t0 += TILE) {
        const size_t mbase = (size_t)b*SEQ + t0;
#pragma unroll
        for (int it = 0; it < 4; it++) {
            int idx = it*512 + tid;
            int r = idx >> 6, c = idx & 63;
            const float* rowp = g_conv + (mbase + r)*CONVD + DIN;
            if (c < 32) *(float4*)&sB[r][c*4]      = *(const float4*)(rowp + c*4);
            else        *(float4*)&sC[r][(c-32)*4] = *(const float4*)(rowp + DSTATE + (c-32)*4);
        }
        {
            int r = tid >> 4, c = tid & 15;
            *(float4*)&sX[r][c*4] =
                *(const float4*)(g_conv + (mbase + r)*CONVD + h*HDIM + c*4);
        }
        if (tid < TILE) {
            float dtv = g_dt[(mbase + tid)*NHEAD + h];
            s_dt[tid]   = dtv;
            s_eadt[tid] = expf(A * dtv);
        }
        __syncthreads();

        for (int ll = 0; ll < TILE; ll++) {
            float e = s_eadt[ll];
            float f = s_dt[ll] * sX[ll][p];
            float part = 0.f;
#pragma unroll
            for (int j = 0; j < 8; j++) {
                int col = j*16 + q*2;
                float2 bb = *(const float2*)&sB[ll][col];
                float2 cc = *(const float2*)&sC[ll][col];
                H[2*j]   = e*H[2*j]   + f*bb.x;
                H[2*j+1] = e*H[2*j+1] + f*bb.y;
                part += cc.x*H[2*j] + cc.y*H[2*j+1];
            }
            part += __shfl_down_sync(0xffffffffu, part, 4, 8);
            part += __shfl_down_sync(0xffffffffu, part, 2, 8);
            part += __shfl_down_sync(0xffffffffu, part, 1, 8);
            if (q == 0)
                g_y[(mbase + ll)*DIN + h*HDIM + p] = part + Dh * sX[ll][p];
        }
        __syncthreads();
    }
}

// ---------------- gated RMSNorm -> bf16 hi/lo planes ----------------
__global__ void __launch_bounds__(256) rmsnorm_kernel(const float* __restrict__ w)
{
    int m = blockIdx.x;
    int tid = threadIdx.x;
    float prod[16];
    float ss = 0.f;
#pragma unroll
    for (int i = 0; i < 16; i++) {
        int col = i*256 + tid;
        float y = g_y[(size_t)m*DIN + col];
        float z = g_zx[(size_t)m*PROJ + col];
        float p = y * (z / (1.f + expf(-z)));
        prod[i] = p;
        ss += p*p;
    }
    __shared__ float red[256];
    red[tid] = ss;
    __syncthreads();
    for (int off = 128; off; off >>= 1) {
        if (tid < off) red[tid] += red[tid + off];
        __syncthreads();
    }
    float scale = rsqrtf(red[0] / (float)DIN + 1e-5f);
#pragma unroll
    for (int i = 0; i < 16; i++) {
        int col = i*256 + tid;
        float v = prod[i] * scale * w[col];
        __nv_bfloat16 hv = __float2bfloat16_rn(v);
        g_yn_hi[(size_t)m*DIN + col] = hv;
        g_yn_lo[(size_t)m*DIN + col] = __float2bfloat16_rn(v - __bfloat162float(hv));
    }
}

// ---------------- launch ----------------
extern "C" void kernel_launch(void* const* d_in, const int* in_sizes, int n_in,
                              void* d_out, int out_size)
{
    const float* hs   = (const float*)d_in[0];
    const float* w1   = (const float*)d_in[1];
    const float* cw   = (const float*)d_in[2];
    const float* cb   = (const float*)d_in[3];
    const float* dtb  = (const float*)d_in[4];
    const float* alog = (const float*)d_in[5];
    const float* Dv   = (const float*)d_in[6];
    const float* nw   = (const float*)d_in[7];
    const float* w2   = (const float*)d_in[8];
    float* out = (float*)d_out;

    static int smem_set = 0;
    if (!smem_set) {
        cudaFuncSetAttribute(gemm_mma, cudaFuncAttributeMaxDynamicSharedMemorySize, SMT);
        smem_set = 1;
    }

    // 0. pre-convert GEMM inputs to bf16 hi/lo planes
    convert_kernel<<<(MTOK*(size_t)HIDV/4 + 255)/256, 256>>>(hs, 0, MTOK*(size_t)HIDV/4);
    convert_kernel<<<(PROJ*(size_t)HIDV/4 + 255)/256, 256>>>(w1, 1, PROJ*(size_t)HIDV/4);
    convert_kernel<<<(HIDV*(size_t)DIN/4 + 255)/256, 256>>>(w2, 2, HIDV*(size_t)DIN/4);

    // 1. in_proj GEMM: g_zx[8192,8512] = hs @ w1^T
    gemm_mma<<<dim3((PROJ+127)/128, MTOK/128), 256, SMT>>>(0, nullptr, MTOK, PROJ, HIDV);
    // 2. conv + silu
    conv_kernel<<<dim3(MTOK, CONVD/256), 256>>>(cw, cb);
    // 3. dt softplus
    dt_kernel<<<(MTOK*NHEAD)/256, 256>>>(dtb);
    // 4. SSD recurrence
    ssd_kernel<<<dim3(NHEAD, BATCH), 512>>>(alog, Dv);
    // 5. gated rmsnorm -> bf16 hi/lo
    rmsnorm_kernel<<<MTOK, 256>>>(nw);
    // 6. out_proj GEMM: out[8192,2048] = yn @ w2^T
    gemm_mma<<<dim3(HIDV/128, MTOK/128), 256, SMT>>>(1, out, MTOK, HIDV, DIN);
}